// round 10
// baseline (speedup 1.0000x reference)
#include <cuda_runtime.h>
#include <cuda_fp16.h>
#include <math.h>
#include <stdint.h>

#define B_    8
#define T_    12
#define NN_   883
#define DM    152
#define DD2   304
#define SSZ   128
#define NL    3
#define STEPS 288
#define ROWS  (B_*NN_)          /* 7064  */
#define MTOK  (ROWS*T_)         /* 84768 */
#define MTILES ((MTOK+127)/128) /* 663   */

// ---------------- scratch (device globals; no allocs allowed) ----------------
__device__ float  g_s [MTOK];
__device__ float  g_h [MTOK*DM];
__device__ __half g_xn [MTOK*DM];
__device__ __half g_xp [MTOK*DD2];
__device__ __half g_z  [MTOK*DD2];
__device__ __half g_xca[MTOK*DD2];
__device__ __half g_xco[MTOK*DD2];
__device__ __half g_cb [MTOK*DD2];

// transposed fp16 weights: [N rows, K cols]
__device__ __half g_wipdw[NL*2*DD2*DM];   /* 608 x 152 */
__device__ __half g_wcl  [NL*DD2*DD2];
__device__ __half g_w23  [NL*256*DD2];    /* interleaved: row 2j=fc2_j, 2j+1=fc3_j */
__device__ __half g_wf1  [NL*DD2*DD2];
__device__ __half g_wop  [NL*DM*DD2];
__device__ float  g_b23  [NL*256];
__device__ float  g_bipdw[NL*2*DD2];

__device__ __forceinline__ float siluf(float v)     { return v / (1.f + expf(-v)); }
__device__ __forceinline__ float softplusf(float v) { return (v > 20.f) ? v : log1pf(expf(v)); }

__device__ __forceinline__ uint32_t sm2u32(const void* p) {
    uint32_t a;
    asm("{ .reg .u64 t; cvta.to.shared.u64 t, %1; cvt.u32.u64 %0, t; }" : "=r"(a) : "l"(p));
    return a;
}
#define SWZ(o) ((uint32_t)(o) ^ ((((uint32_t)(o)) >> 3) & 0x70u))

__device__ __forceinline__ void ldsm4(uint32_t* r, uint32_t addr) {
    asm volatile("ldmatrix.sync.aligned.m8n8.x4.shared.b16 {%0,%1,%2,%3}, [%4];"
                 : "=r"(r[0]), "=r"(r[1]), "=r"(r[2]), "=r"(r[3]) : "r"(addr));
}
__device__ __forceinline__ void mma16816(float* c, const uint32_t* a, const uint32_t* b) {
    asm volatile("mma.sync.aligned.m16n8k16.row.col.f32.f16.f16.f32 "
                 "{%0,%1,%2,%3}, {%4,%5,%6,%7}, {%8,%9}, {%0,%1,%2,%3};"
                 : "+f"(c[0]), "+f"(c[1]), "+f"(c[2]), "+f"(c[3])
                 : "r"(a[0]), "r"(a[1]), "r"(a[2]), "r"(a[3]), "r"(b[0]), "r"(b[1]));
}
__device__ __forceinline__ void cpa16(uint32_t dst, const void* src, uint32_t sz) {
    asm volatile("cp.async.cg.shared.global [%0], [%1], 16, %2;"
                 :: "r"(dst), "l"(src), "r"(sz) : "memory");
}
__device__ __forceinline__ void cp_commit() {
    asm volatile("cp.async.commit_group;" ::: "memory");
}
template<int N>
__device__ __forceinline__ void cp_wait() {
    asm volatile("cp.async.wait_group %0;" :: "n"(N) : "memory");
}

// ---------------- fused epilogue -------------------------------------------
// EPI: 0 bias->f32 | 3 bias->fp16 | 4 fc1+combine->fp16
//      5 dual fp16: col<DD2 -> xp ; col>=DD2 -> silu -> z
//      6 inline in GEMM (BC pair-product -> atomic s)
template<int EPI>
__device__ __forceinline__ void epi2(int m, int col, int ldc, float v0, float v1,
    const float* __restrict__ bias, float* Cf, __half* Ch, __half* Ch2)
{
    v0 += bias[col]; v1 += bias[col + 1];
    if (EPI == 4) {
        float sv = g_s[m];
        size_t off = (size_t)m * DD2 + col;
        float xc0 = __half2float(g_xco[off]);
        float xc1 = __half2float(g_xco[off + 1]);
        v0 = siluf(xc0 * softplusf(v0) * sv) * __half2float(g_z[off]);
        v1 = siluf(xc1 * softplusf(v1) * sv) * __half2float(g_z[off + 1]);
    }
    if (EPI == 0) {
        *(float2*)(Cf + (size_t)m * ldc + col) = make_float2(v0, v1);
    } else if (EPI == 5) {
        if (col < DD2) {
            *(__half2*)(Ch + (size_t)m * DD2 + col) =
                __halves2half2(__float2half(v0), __float2half(v1));
        } else {
            *(__half2*)(Ch2 + (size_t)m * DD2 + (col - DD2)) =
                __halves2half2(__float2half(siluf(v0)), __float2half(siluf(v1)));
        }
    } else {
        *(__half2*)(Ch + (size_t)m * ldc + col) =
            __halves2half2(__float2half(v0), __float2half(v1));
    }
}

// ---------------- GEMM: C[M,Nw] = epi(A[M,KV] @ B[Nw,KV]^T + bias) -----------
// CTA tile 128(M) x 128(N), K compile-time, 3-stage cp.async ring, 2 CTAs/SM.
#define STA 0
#define STB 16384
#define STG_SZ 32768
#define NSTAGE 3
#define SM_TOTAL (NSTAGE*STG_SZ)

template<int EPI, int KV>
__global__ void __launch_bounds__(256, 2)
mma_gemm(const __half* __restrict__ A, const __half* __restrict__ B,
         const float* __restrict__ bias,
         float* Cf, __half* Ch, __half* Ch2,
         int M, int Nw, int ldc)
{
    extern __shared__ char smem[];
    const uint32_t sb = sm2u32(smem);
    const int tid  = threadIdx.x;
    const int lane = tid & 31;
    const int wid  = tid >> 5;
    const int wm   = wid & 3;      // 0..3 (M)
    const int wn   = wid >> 2;     // 0..1 (N)
    const int m0   = blockIdx.y * 128;
    const int n0   = blockIdx.x * 128;

    float acc[2][8][4];
#pragma unroll
    for (int i = 0; i < 2; i++)
#pragma unroll
        for (int j = 0; j < 8; j++)
#pragma unroll
            for (int q = 0; q < 4; q++) acc[i][j][q] = 0.f;

    constexpr int KST = (KV + 15) >> 4;   // k16 steps
    constexpr int KC  = (KST + 3) >> 2;   // 64-wide chunks

    auto load_stage = [&](int stg, int k0) {
        uint32_t base = sb + stg * STG_SZ;
#pragma unroll
        for (int i = 0; i < 4; i++) {          // A: 128 rows x 64 k
            int idx = tid + i * 256;
            int r = idx >> 3, u = idx & 7;
            int gm = m0 + r, gk = k0 + u * 8;
            bool ok = (gm < M) && (gk < KV);
            size_t go = (size_t)(ok ? gm : 0) * KV + (ok ? gk : 0);
            cpa16(base + STA + SWZ(r * 128 + u * 16), A + go, ok ? 16u : 0u);
        }
#pragma unroll
        for (int i = 0; i < 4; i++) {          // B: 128 rows x 64 k
            int idx = tid + i * 256;
            int r = idx >> 3, u = idx & 7;
            int gn = n0 + r, gk = k0 + u * 8;
            bool ok = (gn < Nw) && (gk < KV);
            size_t go = (size_t)(ok ? gn : 0) * KV + (ok ? gk : 0);
            cpa16(base + STB + SWZ(r * 128 + u * 16), B + go, ok ? 16u : 0u);
        }
    };

    // prologue: prefetch up to 2 chunks
    load_stage(0, 0);
    cp_commit();
    if (KC > 1) { load_stage(1, 64); cp_commit(); }
    else        { cp_commit(); }               // keep group count uniform

#pragma unroll
    for (int c = 0; c < KC; c++) {
        if (c + 2 < KC) load_stage((c + 2) % NSTAGE, (c + 2) << 6);
        cp_commit();                            // possibly-empty group
        cp_wait<2>();                           // chunk c resident
        __syncthreads();

        const uint32_t base = sb + (c % NSTAGE) * STG_SZ;
#pragma unroll
        for (int ks = 0; ks < 4; ks++) {
            if (c * 4 + ks >= KST) break;       // folds: c, KST constexpr
            const int kb = ks * 16;
            uint32_t ah[2][4];
#pragma unroll
            for (int mt = 0; mt < 2; mt++) {
                int row = wm * 32 + mt * 16 + (lane & 15);
                ldsm4(ah[mt], base + STA + SWZ(row * 128 + (kb + (lane >> 4) * 8) * 2));
            }
            const int q = lane >> 3;
            const int rowo = (q >> 1) * 8 + (lane & 7);
            const int ko   = (q & 1) * 8;
            uint32_t bf[8][2];
#pragma unroll
            for (int p = 0; p < 4; p++) {
                int row = wn * 64 + p * 16 + rowo;
                uint32_t r4[4];
                ldsm4(r4, base + STB + SWZ(row * 128 + (kb + ko) * 2));
                bf[2*p][0] = r4[0]; bf[2*p][1] = r4[1];
                bf[2*p+1][0] = r4[2]; bf[2*p+1][1] = r4[3];
            }
#pragma unroll
            for (int mt = 0; mt < 2; mt++)
#pragma unroll
                for (int nt = 0; nt < 8; nt++)
                    mma16816(acc[mt][nt], ah[mt], bf[nt]);
        }
        __syncthreads();
    }

    // ---- epilogue ----
    if (EPI == 6) {
#pragma unroll
        for (int mt = 0; mt < 2; mt++) {
            int r0 = m0 + wm * 32 + mt * 16 + (lane >> 2);
            int r1 = r0 + 8;
            float s0 = 0.f, s1 = 0.f;
#pragma unroll
            for (int nt = 0; nt < 8; nt++) {
                int col = n0 + wn * 64 + nt * 8 + (lane & 3) * 2;
                if (col < Nw) {
                    float b0 = bias[col], b1 = bias[col + 1];
                    s0 += (acc[mt][nt][0] + b0) * (acc[mt][nt][1] + b1);
                    s1 += (acc[mt][nt][2] + b0) * (acc[mt][nt][3] + b1);
                }
            }
            if (r0 < M) atomicAdd(&g_s[r0], s0);
            if (r1 < M) atomicAdd(&g_s[r1], s1);
        }
    } else {
#pragma unroll
        for (int mt = 0; mt < 2; mt++) {
            int r0 = m0 + wm * 32 + mt * 16 + (lane >> 2);
            int r1 = r0 + 8;
#pragma unroll
            for (int nt = 0; nt < 8; nt++) {
                int col = n0 + wn * 64 + nt * 8 + (lane & 3) * 2;
                if (col < Nw) {
                    if (r0 < M) epi2<EPI>(r0, col, ldc, acc[mt][nt][0], acc[mt][nt][1], bias, Cf, Ch, Ch2);
                    if (r1 < M) epi2<EPI>(r1, col, ldc, acc[mt][nt][2], acc[mt][nt][3], bias, Cf, Ch, Ch2);
                }
            }
        }
    }
}

// ---------------- weight prep (ONE launch) -----------------------------------
#define SEG_CL  (DD2*DD2)
#define SEG_23  (256*DD2)
#define SEG_F1  (DD2*DD2)
#define SEG_OP  (DM*DD2)
#define SEG_ALL (SEG_CL+SEG_23+SEG_F1+SEG_OP)
#define R0_END  (NL*2*DD2*DM)
#define R1_END  (R0_END + NL*SEG_ALL)
#define R2_END  (R1_END + NL*2*DD2 + NL*256)

__global__ void wprep_all(const float* __restrict__ inw, const float* __restrict__ dww,
                          const float* __restrict__ cl, const float* __restrict__ f2,
                          const float* __restrict__ f3, const float* __restrict__ f1,
                          const float* __restrict__ op,
                          const float* __restrict__ inb, const float* __restrict__ db,
                          const float* __restrict__ f2b, const float* __restrict__ f3b)
{
    int idx = blockIdx.x * blockDim.x + threadIdx.x;
    if (idx < R0_END) {
        const int PER = 2 * DD2 * DM;
        int l = idx / PER, q = idx % PER;
        int n = q / DM, k = q % DM;
        float v = (n < DD2) ? inw[(size_t)l*DM*DD2 + k*DD2 + n]
                            : dww[(size_t)l*DM*DD2 + k*DD2 + (n - DD2)];
        g_wipdw[idx] = __float2half(v);
    } else if (idx < R1_END) {
        int t = idx - R0_END;
        int l = t / SEG_ALL, r = t % SEG_ALL;
        if (r < SEG_CL) {
            int n = r / DD2, k = r % DD2;
            g_wcl[(long)l*SEG_CL + r] = __float2half(cl[(size_t)l*SEG_CL + (size_t)k*DD2 + n]);
        } else if (r < SEG_CL + SEG_23) {
            int q = r - SEG_CL;
            int n = q / DD2, k = q % DD2;
            int j = n >> 1;
            float v = (n & 1) ? f3[(size_t)l*DD2*SSZ + (size_t)k*SSZ + j]
                              : f2[(size_t)l*DD2*SSZ + (size_t)k*SSZ + j];
            g_w23[(long)l*SEG_23 + q] = __float2half(v);
        } else if (r < SEG_CL + SEG_23 + SEG_F1) {
            int q = r - SEG_CL - SEG_23;
            int n = q / DD2, k = q % DD2;
            g_wf1[(long)l*SEG_F1 + q] = __float2half(f1[(size_t)l*SEG_F1 + (size_t)k*DD2 + n]);
        } else {
            int q = r - SEG_CL - SEG_23 - SEG_F1;
            int n = q / DD2, k = q % DD2;
            g_wop[(long)l*SEG_OP + q] = __float2half(op[(size_t)l*SEG_OP + (size_t)k*DM + n]);
        }
    } else if (idx < R2_END) {
        int t = idx - R1_END;
        const int N1 = NL * 2 * DD2;
        if (t < N1) {
            int l = t / (2*DD2), j = t % (2*DD2);
            g_bipdw[t] = (j < DD2) ? inb[l*DD2 + j] : db[l*DD2 + (j - DD2)];
        } else {
            int q = t - N1;
            int l = q / 256, j = q % 256;
            g_b23[q] = (j & 1) ? f3b[l*SSZ + (j >> 1)] : f2b[l*SSZ + (j >> 1)];
        }
    }
}

// ---------------- embedding (f32 h) ------------------------------------------
__global__ void embed_kernel(const float* __restrict__ x, const float* __restrict__ W_in,
                             const float* __restrict__ b_in, const float* __restrict__ tod,
                             const float* __restrict__ dow, const float* __restrict__ adp)
{
    long idx = blockIdx.x * (long)blockDim.x + threadIdx.x;
    if (idx >= (long)MTOK * DM) return;
    int  c      = (int)(idx % DM);
    long tokidx = idx / DM;
    int  t      = (int)(tokidx % T_);
    long rn     = tokidx / T_;
    int  n      = (int)(rn % NN_);
    int  b      = (int)(rn / NN_);
    const float* xe = x + (((long)(b * T_ + t) * NN_ + n) * 3);
    float v;
    if (c < 24) {
        v = b_in[c] + xe[0]*W_in[c] + xe[1]*W_in[24+c] + xe[2]*W_in[48+c];
    } else if (c < 48) {
        int ti = (int)(xe[1] * (float)STEPS);
        ti = min(max(ti, 0), STEPS - 1);
        v = tod[ti*24 + (c-24)];
    } else if (c < 72) {
        int di = (int)xe[2];
        di = min(max(di, 0), 6);
        v = dow[di*24 + (c-48)];
    } else {
        v = adp[((long)t * NN_ + n) * 80 + (c - 72)];
    }
    g_h[idx] = v;
}

// ---------------- rmsnorm (f32 in, fp16 out) ; zeroes g_s --------------------
__global__ void rmsnorm_kernel(const float* __restrict__ w)
{
    int gwarp = (blockIdx.x * blockDim.x + threadIdx.x) >> 5;
    int lane  = threadIdx.x & 31;
    if (gwarp >= MTOK) return;
    const float* row = g_h + (long)gwarp * DM;
    float ss = 0.f;
    for (int c = lane; c < DM; c += 32) { float v = row[c]; ss += v * v; }
#pragma unroll
    for (int o = 16; o; o >>= 1) ss += __shfl_xor_sync(0xffffffffu, ss, o);
    float scale = rsqrtf(ss / (float)DM + 1e-5f);
    long base = (long)gwarp * DM;
    for (int c = lane; c < DM; c += 32)
        g_xn[base + c] = __float2half(row[c] * scale * w[c]);
    if (!lane) g_s[gwarp] = 0.f;
}

// ---------------- conv over T + silu -> fp16 (warp-aligned shfl) -------------
#define DCHUNKS 10
__global__ void conv_silu_kernel(const float* __restrict__ cw, const float* __restrict__ cb)
{
    __shared__ float w[T_*T_*3];
    __shared__ float bsh[T_];
    for (int i = threadIdx.x; i < T_*T_*3; i += blockDim.x) w[i] = cw[i];
    for (int i = threadIdx.x; i < T_;      i += blockDim.x) bsh[i] = cb[i];
    __syncthreads();

    int gw = (int)((blockIdx.x * (long)blockDim.x + threadIdx.x) >> 5);
    if (gw >= ROWS * DCHUNKS) return;
    int lane = threadIdx.x & 31;
    int r  = gw / DCHUNKS;
    int dc = gw % DCHUNKS;
    int d  = dc * 32 + lane;
    int dl = min(d, DD2 - 1);
    const __half* xrow = g_xp + (long)r * (T_ * DD2);

    float v1[T_];
#pragma unroll
    for (int ti = 0; ti < T_; ti++) v1[ti] = __half2float(xrow[ti*DD2 + dl]);

    float acc[T_];
#pragma unroll
    for (int to = 0; to < T_; to++) acc[to] = bsh[to];

#pragma unroll
    for (int ti = 0; ti < T_; ti++) {
        float v0 = __shfl_up_sync(0xffffffffu, v1[ti], 1);
        float v2 = __shfl_down_sync(0xffffffffu, v1[ti], 1);
        if (lane == 0)  v0 = (d > 0) ? __half2float(xrow[ti*DD2 + d - 1]) : 0.f;
        if (lane == 31) v2 = (d < DD2 - 1) ? __half2float(xrow[ti*DD2 + d + 1]) : 0.f;
        if (d >= DD2 - 1) v2 = 0.f;
#pragma unroll
        for (int to = 0; to < T_; to++) {
            const float* wp = &w[(to*T_ + ti)*3];
            acc[to] += v0*wp[0] + v1[ti]*wp[1] + v2*wp[2];
        }
    }
    if (d < DD2) {
        long obase = (long)r * (T_ * DD2) + d;
#pragma unroll
        for (int to = 0; to < T_; to++)
            g_xca[obase + to*DD2] = __float2half(siluf(acc[to]));
    }
}

// ---------------- head: smem-cached W_out, 16 rows/block, f32 h --------------
#define OUTR 16
__global__ void out_kernel(const float* __restrict__ Wout, const float* __restrict__ bout,
                           float* __restrict__ out)
{
    extern __shared__ float ws[];   // [12][1824] transposed
    for (int i = threadIdx.x; i < T_*DM*12; i += 384) {
        int k = i / 12, j = i % 12;
        ws[j * (T_*DM) + k] = Wout[i];
    }
    __syncthreads();
    int wj   = threadIdx.x >> 5;    // 0..11
    int lane = threadIdx.x & 31;
    const float* wcol = ws + wj * (T_*DM);
    for (int rr = 0; rr < OUTR; rr++) {
        int rn = blockIdx.x * OUTR + rr;
        if (rn >= ROWS) break;
        const float4* row = (const float4*)(g_h + (long)rn * (T_*DM));
        float acc = 0.f;
        for (int k4 = lane; k4 < (T_*DM)/4; k4 += 32) {
            float4 hv = row[k4];
            acc += hv.x * wcol[4*k4] + hv.y * wcol[4*k4+1]
                 + hv.z * wcol[4*k4+2] + hv.w * wcol[4*k4+3];
        }
#pragma unroll
        for (int o = 16; o; o >>= 1) acc += __shfl_xor_sync(0xffffffffu, acc, o);
        if (!lane) {
            int n = rn % NN_, b = rn / NN_;
            out[((long)b * 12 + wj) * NN_ + n] = acc + bout[wj];
        }
    }
}

// =============================================================================
extern "C" void kernel_launch(void* const* d_in, const int* in_sizes, int n_in,
                              void* d_out, int out_size)
{
    (void)in_sizes; (void)n_in; (void)out_size;
    const float* x        = (const float*)d_in[0];
    const float* W_in     = (const float*)d_in[1];
    const float* b_in     = (const float*)d_in[2];
    const float* tod      = (const float*)d_in[3];
    const float* dow      = (const float*)d_in[4];
    const float* adp      = (const float*)d_in[5];
    const float* norm_w   = (const float*)d_in[6];
    const float* inproj_w = (const float*)d_in[7];
    const float* inproj_b = (const float*)d_in[8];
    const float* conv_w   = (const float*)d_in[9];
    const float* conv_b   = (const float*)d_in[10];
    const float* convlin_w= (const float*)d_in[11];
    const float* convlin_b= (const float*)d_in[12];
    const float* fc1_w    = (const float*)d_in[13];
    const float* fc1_b    = (const float*)d_in[14];
    const float* fc2_w    = (const float*)d_in[15];
    const float* fc2_b    = (const float*)d_in[16];
    const float* fc3_w    = (const float*)d_in[17];
    const float* fc3_b    = (const float*)d_in[18];
    /* d_in[19] = A_ssm unused (h0 == 0) */
    const float* D_w      = (const float*)d_in[20];
    const float* D_b      = (const float*)d_in[21];
    const float* outproj_w= (const float*)d_in[22];
    const float* outproj_b= (const float*)d_in[23];
    const float* W_out    = (const float*)d_in[24];
    const float* b_out    = (const float*)d_in[25];
    float* out = (float*)d_out;

    cudaFuncSetAttribute((const void*)mma_gemm<5,152>, cudaFuncAttributeMaxDynamicSharedMemorySize, SM_TOTAL);
    cudaFuncSetAttribute((const void*)mma_gemm<3,304>, cudaFuncAttributeMaxDynamicSharedMemorySize, SM_TOTAL);
    cudaFuncSetAttribute((const void*)mma_gemm<6,304>, cudaFuncAttributeMaxDynamicSharedMemorySize, SM_TOTAL);
    cudaFuncSetAttribute((const void*)mma_gemm<4,304>, cudaFuncAttributeMaxDynamicSharedMemorySize, SM_TOTAL);
    cudaFuncSetAttribute((const void*)mma_gemm<0,304>, cudaFuncAttributeMaxDynamicSharedMemorySize, SM_TOTAL);
    cudaFuncSetAttribute((const void*)out_kernel, cudaFuncAttributeMaxDynamicSharedMemorySize,
                         T_*DM*12*(int)sizeof(float));

    void* p;
#define SYM(sym, var, ty) cudaGetSymbolAddress(&p, sym); ty* var = (ty*)p;
    SYM(g_b23,   b23_p,  float)
    SYM(g_bipdw, bipdw_p,float)
    SYM(g_h,     h_p,    float)
    SYM(g_xn,    xn_p,   __half)
    SYM(g_xp,    xp_p,   __half)
    SYM(g_z,     z_p,    __half)
    SYM(g_xca,   xca_p,  __half)
    SYM(g_xco,   xco_p,  __half)
    SYM(g_cb,    cb_p,   __half)
    SYM(g_wipdw, wpd_p,  __half)
    SYM(g_wcl,   wcl_p,  __half)
    SYM(g_w23,   w23_p,  __half)
    SYM(g_wf1,   wf1_p,  __half)
    SYM(g_wop,   wop_p,  __half)
#undef SYM

    // launch 0: embedding
    {
        long tot = (long)MTOK * DM;
        embed_kernel<<<(int)((tot + 255)/256), 256>>>(x, W_in, b_in, tod, dow, adp);
    }
    // launch 1: rmsnorm layer 0
    rmsnorm_kernel<<<(MTOK*32 + 255)/256, 256>>>(norm_w);
    // launch 2: all weight prep
    wprep_all<<<(R2_END + 255)/256, 256>>>(inproj_w, D_w, convlin_w, fc2_w, fc3_w,
                                           fc1_w, outproj_w, inproj_b, D_b, fc2_b, fc3_b);

    for (int i = 0; i < NL; i++) {
        if (i > 0)
            rmsnorm_kernel<<<(MTOK*32 + 255)/256, 256>>>(norm_w + i*DM);

        // fused inproj|D_w : xn(152) -> xp(fp16) & z(fp16 silu), N=608
        mma_gemm<5,152><<<dim3(5, MTILES), 256, SM_TOTAL>>>(xn_p,
            wpd_p + (long)i*2*DD2*DM, bipdw_p + (long)i*2*DD2,
            nullptr, xp_p, z_p, MTOK, 2*DD2, DD2);

        conv_silu_kernel<<<(ROWS*DCHUNKS*32 + 255)/256, 256>>>(conv_w + i*T_*T_*3, conv_b + i*T_);

        // convlin: xca(304) -> xco fp16(304)
        mma_gemm<3,304><<<dim3(3, MTILES), 256, SM_TOTAL>>>(xca_p,
            wcl_p + (long)i*DD2*DD2, convlin_b + i*DD2,
            nullptr, xco_p, nullptr, MTOK, DD2, DD2);

        // fc2|fc3 interleaved: epilogue computes s via pair products + atomics
        mma_gemm<6,304><<<dim3(2, MTILES), 256, SM_TOTAL>>>(xco_p,
            w23_p + (long)i*256*DD2, b23_p + i*256,
            nullptr, nullptr, nullptr, MTOK, 256, 256);

        // fc1 + combine fused: -> cb fp16(304)
        mma_gemm<4,304><<<dim3(3, MTILES), 256, SM_TOTAL>>>(xco_p,
            wf1_p + (long)i*DD2*DD2, fc1_b + i*DD2,
            nullptr, cb_p, nullptr, MTOK, DD2, DD2);

        // outproj: cb(304) -> h f32(152)
        mma_gemm<0,304><<<dim3(2, MTILES), 256, SM_TOTAL>>>(cb_p,
            wop_p + (long)i*DM*DD2, outproj_b + i*DM,
            h_p, nullptr, nullptr, MTOK, DM, DM);
    }

    out_kernel<<<(ROWS + OUTR - 1)/OUTR, 384, T_*DM*12*sizeof(float)>>>(W_out, b_out, out);
}

// round 11
// speedup vs baseline: 1.0826x; 1.0826x over previous
#include <cuda_runtime.h>
#include <cuda_fp16.h>
#include <math.h>
#include <stdint.h>

#define B_    8
#define T_    12
#define NN_   883
#define DM    152
#define DD2   304
#define SSZ   128
#define NL    3
#define STEPS 288
#define ROWS  (B_*NN_)          /* 7064  */
#define MTOK  (ROWS*T_)         /* 84768 */
#define MTILES ((MTOK+127)/128) /* 663   */

// ---------------- scratch (device globals; no allocs allowed) ----------------
__device__ float  g_s [MTOK];
__device__ float  g_h [MTOK*DM];
__device__ __half g_xn [MTOK*DM];
__device__ __half g_xp [MTOK*DD2];
__device__ __half g_z  [MTOK*DD2];
__device__ __half g_xca[MTOK*DD2];
__device__ __half g_xco[MTOK*DD2];
__device__ __half g_cb [MTOK*DD2];

// transposed fp16 weights: [N rows, K cols]
__device__ __half g_wipdw[NL*2*DD2*DM];   /* 608 x 152 */
__device__ __half g_wcl  [NL*DD2*DD2];
__device__ __half g_w23  [NL*256*DD2];    /* interleaved: row 2j=fc2_j, 2j+1=fc3_j */
__device__ __half g_wf1  [NL*DD2*DD2];
__device__ __half g_wop  [NL*DM*DD2];
__device__ float  g_b23  [NL*256];
__device__ float  g_bipdw[NL*2*DD2];

__device__ __forceinline__ float siluf(float v)     { return v / (1.f + expf(-v)); }
__device__ __forceinline__ float softplusf(float v) { return (v > 20.f) ? v : log1pf(expf(v)); }

__device__ __forceinline__ uint32_t sm2u32(const void* p) {
    uint32_t a;
    asm("{ .reg .u64 t; cvta.to.shared.u64 t, %1; cvt.u32.u64 %0, t; }" : "=r"(a) : "l"(p));
    return a;
}
#define SWZ(o) ((uint32_t)(o) ^ ((((uint32_t)(o)) >> 3) & 0x70u))

__device__ __forceinline__ void ldsm4(uint32_t* r, uint32_t addr) {
    asm volatile("ldmatrix.sync.aligned.m8n8.x4.shared.b16 {%0,%1,%2,%3}, [%4];"
                 : "=r"(r[0]), "=r"(r[1]), "=r"(r[2]), "=r"(r[3]) : "r"(addr));
}
__device__ __forceinline__ void mma16816(float* c, const uint32_t* a, const uint32_t* b) {
    asm volatile("mma.sync.aligned.m16n8k16.row.col.f32.f16.f16.f32 "
                 "{%0,%1,%2,%3}, {%4,%5,%6,%7}, {%8,%9}, {%0,%1,%2,%3};"
                 : "+f"(c[0]), "+f"(c[1]), "+f"(c[2]), "+f"(c[3])
                 : "r"(a[0]), "r"(a[1]), "r"(a[2]), "r"(a[3]), "r"(b[0]), "r"(b[1]));
}
__device__ __forceinline__ void cpa16(uint32_t dst, const void* src, uint32_t sz) {
    asm volatile("cp.async.cg.shared.global [%0], [%1], 16, %2;"
                 :: "r"(dst), "l"(src), "r"(sz) : "memory");
}
__device__ __forceinline__ void cp_commit() {
    asm volatile("cp.async.commit_group;" ::: "memory");
}
template<int N>
__device__ __forceinline__ void cp_wait() {
    asm volatile("cp.async.wait_group %0;" :: "n"(N) : "memory");
}

// ---------------- fused epilogue -------------------------------------------
// EPI: 0 bias->f32 | 3 bias->fp16 | 4 fc1+combine->fp16
//      5 dual fp16: col<DD2 -> xp ; col>=DD2 -> silu -> z
//      6 inline in GEMM (BC pair-product -> atomic s)
template<int EPI>
__device__ __forceinline__ void epi2(int m, int col, int ldc, float v0, float v1,
    const float* __restrict__ bias, float* Cf, __half* Ch, __half* Ch2)
{
    v0 += bias[col]; v1 += bias[col + 1];
    if (EPI == 4) {
        float sv = g_s[m];
        size_t off = (size_t)m * DD2 + col;
        float xc0 = __half2float(g_xco[off]);
        float xc1 = __half2float(g_xco[off + 1]);
        v0 = siluf(xc0 * softplusf(v0) * sv) * __half2float(g_z[off]);
        v1 = siluf(xc1 * softplusf(v1) * sv) * __half2float(g_z[off + 1]);
    }
    if (EPI == 0) {
        *(float2*)(Cf + (size_t)m * ldc + col) = make_float2(v0, v1);
    } else if (EPI == 5) {
        if (col < DD2) {
            *(__half2*)(Ch + (size_t)m * DD2 + col) =
                __halves2half2(__float2half(v0), __float2half(v1));
        } else {
            *(__half2*)(Ch2 + (size_t)m * DD2 + (col - DD2)) =
                __halves2half2(__float2half(siluf(v0)), __float2half(siluf(v1)));
        }
    } else {
        *(__half2*)(Ch + (size_t)m * ldc + col) =
            __halves2half2(__float2half(v0), __float2half(v1));
    }
}

// ---------------- pipelined chunk compute (NKS k-steps) -----------------------
// B-fragments are software-pipelined: ldsm of fragment p+1 issues between
// the MMAs of fragment p, putting ~4 MMAs in every LDSM shadow.
#define STA 0
#define STB 16384
#define STG_SZ 32768
#define SM_TOTAL (2*STG_SZ)

template<int NKS>
__device__ __forceinline__ void gemm_chunk(uint32_t base, int wm, int wn, int lane,
                                           float acc[2][8][4])
{
    const int q    = lane >> 3;
    const int rowo = (q >> 1) * 8 + (lane & 7);
    const int ko   = (q & 1) * 8;
#pragma unroll
    for (int ks = 0; ks < NKS; ks++) {
        const int kb = ks * 16;
        uint32_t ah[2][4];
#pragma unroll
        for (int mt = 0; mt < 2; mt++) {
            int row = wm * 32 + mt * 16 + (lane & 15);
            ldsm4(ah[mt], base + STA + SWZ(row * 128 + (kb + (lane >> 4) * 8) * 2));
        }
        uint32_t rb[4];
        {
            int row = wn * 64 + rowo;
            ldsm4(rb, base + STB + SWZ(row * 128 + (kb + ko) * 2));
        }
#pragma unroll
        for (int p = 0; p < 4; p++) {
            uint32_t rnx[4];
            if (p < 3) {
                int row = wn * 64 + (p + 1) * 16 + rowo;
                ldsm4(rnx, base + STB + SWZ(row * 128 + (kb + ko) * 2));
            }
            uint32_t b0[2] = {rb[0], rb[1]}, b1[2] = {rb[2], rb[3]};
            mma16816(acc[0][2*p],   ah[0], b0);
            mma16816(acc[0][2*p+1], ah[0], b1);
            mma16816(acc[1][2*p],   ah[1], b0);
            mma16816(acc[1][2*p+1], ah[1], b1);
            if (p < 3) { rb[0]=rnx[0]; rb[1]=rnx[1]; rb[2]=rnx[2]; rb[3]=rnx[3]; }
        }
    }
}

// ---------------- GEMM: C[M,Nw] = epi(A[M,KV] @ B[Nw,KV]^T + bias) -----------
// CTA tile 128(M) x 128(N), 2-stage cp.async (R8 structure), 2 CTAs/SM.
template<int EPI, int KV>
__global__ void __launch_bounds__(256, 2)
mma_gemm(const __half* __restrict__ A, const __half* __restrict__ B,
         const float* __restrict__ bias,
         float* Cf, __half* Ch, __half* Ch2,
         int M, int Nw, int ldc)
{
    extern __shared__ char smem[];
    const uint32_t sb = sm2u32(smem);
    const int tid  = threadIdx.x;
    const int lane = tid & 31;
    const int wid  = tid >> 5;
    const int wm   = wid & 3;      // 0..3 (M)
    const int wn   = wid >> 2;     // 0..1 (N)
    const int m0   = blockIdx.y * 128;
    const int n0   = blockIdx.x * 128;

    float acc[2][8][4];
#pragma unroll
    for (int i = 0; i < 2; i++)
#pragma unroll
        for (int j = 0; j < 8; j++)
#pragma unroll
            for (int q = 0; q < 4; q++) acc[i][j][q] = 0.f;

    constexpr int KST  = (KV + 15) >> 4;    // total k16 steps
    constexpr int KC   = (KST + 3) >> 2;    // chunks
    constexpr int TAIL = KST - ((KST >> 2) << 2);  // ksteps in last partial chunk (0 if full)

    auto load_stage = [&](int stg, int k0) {
        uint32_t base = sb + stg * STG_SZ;
#pragma unroll
        for (int i = 0; i < 4; i++) {          // A: 128 rows x 64 k
            int idx = tid + i * 256;
            int r = idx >> 3, u = idx & 7;
            int gm = m0 + r, gk = k0 + u * 8;
            bool ok = (gm < M) && (gk < KV);
            size_t go = (size_t)(ok ? gm : 0) * KV + (ok ? gk : 0);
            cpa16(base + STA + SWZ(r * 128 + u * 16), A + go, ok ? 16u : 0u);
        }
#pragma unroll
        for (int i = 0; i < 4; i++) {          // B: 128 rows x 64 k
            int idx = tid + i * 256;
            int r = idx >> 3, u = idx & 7;
            int gn = n0 + r, gk = k0 + u * 8;
            bool ok = (gn < Nw) && (gk < KV);
            size_t go = (size_t)(ok ? gn : 0) * KV + (ok ? gk : 0);
            cpa16(base + STB + SWZ(r * 128 + u * 16), B + go, ok ? 16u : 0u);
        }
    };

    load_stage(0, 0);
    cp_commit();

    for (int c = 0; c < KC; c++) {
        if (c + 1 < KC) {
            load_stage((c + 1) & 1, (c + 1) << 6);
            cp_commit();
            cp_wait<1>();
        } else {
            cp_wait<0>();
        }
        __syncthreads();

        const uint32_t base = sb + (c & 1) * STG_SZ;
        if (TAIL == 0 || c < KC - 1)
            gemm_chunk<4>(base, wm, wn, lane, acc);
        else
            gemm_chunk<TAIL ? TAIL : 4>(base, wm, wn, lane, acc);
        __syncthreads();
    }

    // ---- epilogue ----
    if (EPI == 6) {
#pragma unroll
        for (int mt = 0; mt < 2; mt++) {
            int r0 = m0 + wm * 32 + mt * 16 + (lane >> 2);
            int r1 = r0 + 8;
            float s0 = 0.f, s1 = 0.f;
#pragma unroll
            for (int nt = 0; nt < 8; nt++) {
                int col = n0 + wn * 64 + nt * 8 + (lane & 3) * 2;
                if (col < Nw) {
                    float b0 = bias[col], b1 = bias[col + 1];
                    s0 += (acc[mt][nt][0] + b0) * (acc[mt][nt][1] + b1);
                    s1 += (acc[mt][nt][2] + b0) * (acc[mt][nt][3] + b1);
                }
            }
            if (r0 < M) atomicAdd(&g_s[r0], s0);
            if (r1 < M) atomicAdd(&g_s[r1], s1);
        }
    } else {
#pragma unroll
        for (int mt = 0; mt < 2; mt++) {
            int r0 = m0 + wm * 32 + mt * 16 + (lane >> 2);
            int r1 = r0 + 8;
#pragma unroll
            for (int nt = 0; nt < 8; nt++) {
                int col = n0 + wn * 64 + nt * 8 + (lane & 3) * 2;
                if (col < Nw) {
                    if (r0 < M) epi2<EPI>(r0, col, ldc, acc[mt][nt][0], acc[mt][nt][1], bias, Cf, Ch, Ch2);
                    if (r1 < M) epi2<EPI>(r1, col, ldc, acc[mt][nt][2], acc[mt][nt][3], bias, Cf, Ch, Ch2);
                }
            }
        }
    }
}

// ---------------- weight prep (ONE launch) -----------------------------------
#define SEG_CL  (DD2*DD2)
#define SEG_23  (256*DD2)
#define SEG_F1  (DD2*DD2)
#define SEG_OP  (DM*DD2)
#define SEG_ALL (SEG_CL+SEG_23+SEG_F1+SEG_OP)
#define R0_END  (NL*2*DD2*DM)
#define R1_END  (R0_END + NL*SEG_ALL)
#define R2_END  (R1_END + NL*2*DD2 + NL*256)

__global__ void wprep_all(const float* __restrict__ inw, const float* __restrict__ dww,
                          const float* __restrict__ cl, const float* __restrict__ f2,
                          const float* __restrict__ f3, const float* __restrict__ f1,
                          const float* __restrict__ op,
                          const float* __restrict__ inb, const float* __restrict__ db,
                          const float* __restrict__ f2b, const float* __restrict__ f3b)
{
    int idx = blockIdx.x * blockDim.x + threadIdx.x;
    if (idx < R0_END) {
        const int PER = 2 * DD2 * DM;
        int l = idx / PER, q = idx % PER;
        int n = q / DM, k = q % DM;
        float v = (n < DD2) ? inw[(size_t)l*DM*DD2 + k*DD2 + n]
                            : dww[(size_t)l*DM*DD2 + k*DD2 + (n - DD2)];
        g_wipdw[idx] = __float2half(v);
    } else if (idx < R1_END) {
        int t = idx - R0_END;
        int l = t / SEG_ALL, r = t % SEG_ALL;
        if (r < SEG_CL) {
            int n = r / DD2, k = r % DD2;
            g_wcl[(long)l*SEG_CL + r] = __float2half(cl[(size_t)l*SEG_CL + (size_t)k*DD2 + n]);
        } else if (r < SEG_CL + SEG_23) {
            int q = r - SEG_CL;
            int n = q / DD2, k = q % DD2;
            int j = n >> 1;
            float v = (n & 1) ? f3[(size_t)l*DD2*SSZ + (size_t)k*SSZ + j]
                              : f2[(size_t)l*DD2*SSZ + (size_t)k*SSZ + j];
            g_w23[(long)l*SEG_23 + q] = __float2half(v);
        } else if (r < SEG_CL + SEG_23 + SEG_F1) {
            int q = r - SEG_CL - SEG_23;
            int n = q / DD2, k = q % DD2;
            g_wf1[(long)l*SEG_F1 + q] = __float2half(f1[(size_t)l*SEG_F1 + (size_t)k*DD2 + n]);
        } else {
            int q = r - SEG_CL - SEG_23 - SEG_F1;
            int n = q / DD2, k = q % DD2;
            g_wop[(long)l*SEG_OP + q] = __float2half(op[(size_t)l*SEG_OP + (size_t)k*DM + n]);
        }
    } else if (idx < R2_END) {
        int t = idx - R1_END;
        const int N1 = NL * 2 * DD2;
        if (t < N1) {
            int l = t / (2*DD2), j = t % (2*DD2);
            g_bipdw[t] = (j < DD2) ? inb[l*DD2 + j] : db[l*DD2 + (j - DD2)];
        } else {
            int q = t - N1;
            int l = q / 256, j = q % 256;
            g_b23[q] = (j & 1) ? f3b[l*SSZ + (j >> 1)] : f2b[l*SSZ + (j >> 1)];
        }
    }
}

// ---------------- embedding (f32 h) ------------------------------------------
__global__ void embed_kernel(const float* __restrict__ x, const float* __restrict__ W_in,
                             const float* __restrict__ b_in, const float* __restrict__ tod,
                             const float* __restrict__ dow, const float* __restrict__ adp)
{
    long idx = blockIdx.x * (long)blockDim.x + threadIdx.x;
    if (idx >= (long)MTOK * DM) return;
    int  c      = (int)(idx % DM);
    long tokidx = idx / DM;
    int  t      = (int)(tokidx % T_);
    long rn     = tokidx / T_;
    int  n      = (int)(rn % NN_);
    int  b      = (int)(rn / NN_);
    const float* xe = x + (((long)(b * T_ + t) * NN_ + n) * 3);
    float v;
    if (c < 24) {
        v = b_in[c] + xe[0]*W_in[c] + xe[1]*W_in[24+c] + xe[2]*W_in[48+c];
    } else if (c < 48) {
        int ti = (int)(xe[1] * (float)STEPS);
        ti = min(max(ti, 0), STEPS - 1);
        v = tod[ti*24 + (c-24)];
    } else if (c < 72) {
        int di = (int)xe[2];
        di = min(max(di, 0), 6);
        v = dow[di*24 + (c-48)];
    } else {
        v = adp[((long)t * NN_ + n) * 80 + (c - 72)];
    }
    g_h[idx] = v;
}

// ---------------- rmsnorm (f32 in, fp16 out) ; zeroes g_s --------------------
__global__ void rmsnorm_kernel(const float* __restrict__ w)
{
    int gwarp = (blockIdx.x * blockDim.x + threadIdx.x) >> 5;
    int lane  = threadIdx.x & 31;
    if (gwarp >= MTOK) return;
    const float* row = g_h + (long)gwarp * DM;
    float ss = 0.f;
    for (int c = lane; c < DM; c += 32) { float v = row[c]; ss += v * v; }
#pragma unroll
    for (int o = 16; o; o >>= 1) ss += __shfl_xor_sync(0xffffffffu, ss, o);
    float scale = rsqrtf(ss / (float)DM + 1e-5f);
    long base = (long)gwarp * DM;
    for (int c = lane; c < DM; c += 32)
        g_xn[base + c] = __float2half(row[c] * scale * w[c]);
    if (!lane) g_s[gwarp] = 0.f;
}

// ---------------- conv over T + silu -> fp16 (warp-aligned shfl) -------------
#define DCHUNKS 10
__global__ void conv_silu_kernel(const float* __restrict__ cw, const float* __restrict__ cb)
{
    __shared__ float w[T_*T_*3];
    __shared__ float bsh[T_];
    for (int i = threadIdx.x; i < T_*T_*3; i += blockDim.x) w[i] = cw[i];
    for (int i = threadIdx.x; i < T_;      i += blockDim.x) bsh[i] = cb[i];
    __syncthreads();

    int gw = (int)((blockIdx.x * (long)blockDim.x + threadIdx.x) >> 5);
    if (gw >= ROWS * DCHUNKS) return;
    int lane = threadIdx.x & 31;
    int r  = gw / DCHUNKS;
    int dc = gw % DCHUNKS;
    int d  = dc * 32 + lane;
    int dl = min(d, DD2 - 1);
    const __half* xrow = g_xp + (long)r * (T_ * DD2);

    float v1[T_];
#pragma unroll
    for (int ti = 0; ti < T_; ti++) v1[ti] = __half2float(xrow[ti*DD2 + dl]);

    float acc[T_];
#pragma unroll
    for (int to = 0; to < T_; to++) acc[to] = bsh[to];

#pragma unroll
    for (int ti = 0; ti < T_; ti++) {
        float v0 = __shfl_up_sync(0xffffffffu, v1[ti], 1);
        float v2 = __shfl_down_sync(0xffffffffu, v1[ti], 1);
        if (lane == 0)  v0 = (d > 0) ? __half2float(xrow[ti*DD2 + d - 1]) : 0.f;
        if (lane == 31) v2 = (d < DD2 - 1) ? __half2float(xrow[ti*DD2 + d + 1]) : 0.f;
        if (d >= DD2 - 1) v2 = 0.f;
#pragma unroll
        for (int to = 0; to < T_; to++) {
            const float* wp = &w[(to*T_ + ti)*3];
            acc[to] += v0*wp[0] + v1[ti]*wp[1] + v2*wp[2];
        }
    }
    if (d < DD2) {
        long obase = (long)r * (T_ * DD2) + d;
#pragma unroll
        for (int to = 0; to < T_; to++)
            g_xca[obase + to*DD2] = __float2half(siluf(acc[to]));
    }
}

// ---------------- head: smem-cached W_out, 16 rows/block, f32 h --------------
#define OUTR 16
__global__ void out_kernel(const float* __restrict__ Wout, const float* __restrict__ bout,
                           float* __restrict__ out)
{
    extern __shared__ float ws[];   // [12][1824] transposed
    for (int i = threadIdx.x; i < T_*DM*12; i += 384) {
        int k = i / 12, j = i % 12;
        ws[j * (T_*DM) + k] = Wout[i];
    }
    __syncthreads();
    int wj   = threadIdx.x >> 5;    // 0..11
    int lane = threadIdx.x & 31;
    const float* wcol = ws + wj * (T_*DM);
    for (int rr = 0; rr < OUTR; rr++) {
        int rn = blockIdx.x * OUTR + rr;
        if (rn >= ROWS) break;
        const float4* row = (const float4*)(g_h + (long)rn * (T_*DM));
        float acc = 0.f;
        for (int k4 = lane; k4 < (T_*DM)/4; k4 += 32) {
            float4 hv = row[k4];
            acc += hv.x * wcol[4*k4] + hv.y * wcol[4*k4+1]
                 + hv.z * wcol[4*k4+2] + hv.w * wcol[4*k4+3];
        }
#pragma unroll
        for (int o = 16; o; o >>= 1) acc += __shfl_xor_sync(0xffffffffu, acc, o);
        if (!lane) {
            int n = rn % NN_, b = rn / NN_;
            out[((long)b * 12 + wj) * NN_ + n] = acc + bout[wj];
        }
    }
}

// =============================================================================
extern "C" void kernel_launch(void* const* d_in, const int* in_sizes, int n_in,
                              void* d_out, int out_size)
{
    (void)in_sizes; (void)n_in; (void)out_size;
    const float* x        = (const float*)d_in[0];
    const float* W_in     = (const float*)d_in[1];
    const float* b_in     = (const float*)d_in[2];
    const float* tod      = (const float*)d_in[3];
    const float* dow      = (const float*)d_in[4];
    const float* adp      = (const float*)d_in[5];
    const float* norm_w   = (const float*)d_in[6];
    const float* inproj_w = (const float*)d_in[7];
    const float* inproj_b = (const float*)d_in[8];
    const float* conv_w   = (const float*)d_in[9];
    const float* conv_b   = (const float*)d_in[10];
    const float* convlin_w= (const float*)d_in[11];
    const float* convlin_b= (const float*)d_in[12];
    const float* fc1_w    = (const float*)d_in[13];
    const float* fc1_b    = (const float*)d_in[14];
    const float* fc2_w    = (const float*)d_in[15];
    const float* fc2_b    = (const float*)d_in[16];
    const float* fc3_w    = (const float*)d_in[17];
    const float* fc3_b    = (const float*)d_in[18];
    /* d_in[19] = A_ssm unused (h0 == 0) */
    const float* D_w      = (const float*)d_in[20];
    const float* D_b      = (const float*)d_in[21];
    const float* outproj_w= (const float*)d_in[22];
    const float* outproj_b= (const float*)d_in[23];
    const float* W_out    = (const float*)d_in[24];
    const float* b_out    = (const float*)d_in[25];
    float* out = (float*)d_out;

    cudaFuncSetAttribute((const void*)mma_gemm<5,152>, cudaFuncAttributeMaxDynamicSharedMemorySize, SM_TOTAL);
    cudaFuncSetAttribute((const void*)mma_gemm<3,304>, cudaFuncAttributeMaxDynamicSharedMemorySize, SM_TOTAL);
    cudaFuncSetAttribute((const void*)mma_gemm<6,304>, cudaFuncAttributeMaxDynamicSharedMemorySize, SM_TOTAL);
    cudaFuncSetAttribute((const void*)mma_gemm<4,304>, cudaFuncAttributeMaxDynamicSharedMemorySize, SM_TOTAL);
    cudaFuncSetAttribute((const void*)mma_gemm<0,304>, cudaFuncAttributeMaxDynamicSharedMemorySize, SM_TOTAL);
    cudaFuncSetAttribute((const void*)out_kernel, cudaFuncAttributeMaxDynamicSharedMemorySize,
                         T_*DM*12*(int)sizeof(float));

    void* p;
#define SYM(sym, var, ty) cudaGetSymbolAddress(&p, sym); ty* var = (ty*)p;
    SYM(g_b23,   b23_p,  float)
    SYM(g_bipdw, bipdw_p,float)
    SYM(g_h,     h_p,    float)
    SYM(g_xn,    xn_p,   __half)
    SYM(g_xp,    xp_p,   __half)
    SYM(g_z,     z_p,    __half)
    SYM(g_xca,   xca_p,  __half)
    SYM(g_xco,   xco_p,  __half)
    SYM(g_cb,    cb_p,   __half)
    SYM(g_wipdw, wpd_p,  __half)
    SYM(g_wcl,   wcl_p,  __half)
    SYM(g_w23,   w23_p,  __half)
    SYM(g_wf1,   wf1_p,  __half)
    SYM(g_wop,   wop_p,  __half)
#undef SYM

    // launch 0: embedding
    {
        long tot = (long)MTOK * DM;
        embed_kernel<<<(int)((tot + 255)/256), 256>>>(x, W_in, b_in, tod, dow, adp);
    }
    // launch 1: rmsnorm layer 0
    rmsnorm_kernel<<<(MTOK*32 + 255)/256, 256>>>(norm_w);
    // launch 2: all weight prep
    wprep_all<<<(R2_END + 255)/256, 256>>>(inproj_w, D_w, convlin_w, fc2_w, fc3_w,
                                           fc1_w, outproj_w, inproj_b, D_b, fc2_b, fc3_b);

    for (int i = 0; i < NL; i++) {
        if (i > 0)
            rmsnorm_kernel<<<(MTOK*32 + 255)/256, 256>>>(norm_w + i*DM);

        // fused inproj|D_w : xn(152) -> xp(fp16) & z(fp16 silu), N=608
        mma_gemm<5,152><<<dim3(5, MTILES), 256, SM_TOTAL>>>(xn_p,
            wpd_p + (long)i*2*DD2*DM, bipdw_p + (long)i*2*DD2,
            nullptr, xp_p, z_p, MTOK, 2*DD2, DD2);

        conv_silu_kernel<<<(ROWS*DCHUNKS*32 + 255)/256, 256>>>(conv_w + i*T_*T_*3, conv_b + i*T_);

        // convlin: xca(304) -> xco fp16(304)
        mma_gemm<3,304><<<dim3(3, MTILES), 256, SM_TOTAL>>>(xca_p,
            wcl_p + (long)i*DD2*DD2, convlin_b + i*DD2,
            nullptr, xco_p, nullptr, MTOK, DD2, DD2);

        // fc2|fc3 interleaved: epilogue computes s via pair products + atomics
        mma_gemm<6,304><<<dim3(2, MTILES), 256, SM_TOTAL>>>(xco_p,
            w23_p + (long)i*256*DD2, b23_p + i*256,
            nullptr, nullptr, nullptr, MTOK, 256, 256);

        // fc1 + combine fused: -> cb fp16(304)
        mma_gemm<4,304><<<dim3(3, MTILES), 256, SM_TOTAL>>>(xco_p,
            wf1_p + (long)i*DD2*DD2, fc1_b + i*DD2,
            nullptr, cb_p, nullptr, MTOK, DD2, DD2);

        // outproj: cb(304) -> h f32(152)
        mma_gemm<0,304><<<dim3(2, MTILES), 256, SM_TOTAL>>>(cb_p,
            wop_p + (long)i*DM*DD2, outproj_b + i*DM,
            h_p, nullptr, nullptr, MTOK, DM, DM);
    }

    out_kernel<<<(ROWS + OUTR - 1)/OUTR, 384, T_*DM*12*sizeof(float)>>>(W_out, b_out, out);
}